// round 4
// baseline (speedup 1.0000x reference)
#include <cuda_runtime.h>

// out[b, r, c] = x[b, r, c] * weight[c], N = 4096.
// Persistent grid-stride kernel. Each chunk = 1024 float4 = exactly one 4096-col
// row, so each thread's weight columns (k*1024 + t*4) are invariant across
// chunks -> hoist weight into registers once. Streaming hints on x/out.

#define THREADS 256
#define UNROLL  4
#define CHUNK   (THREADS * UNROLL)   // 1024 float4 = 4096 scalars = one row

__global__ void __launch_bounds__(THREADS) scale_lastdim_pers_kernel(
    const float4* __restrict__ x4,
    const float*  __restrict__ w,
    float4* __restrict__ out4,
    int nchunks)
{
    const int t = threadIdx.x;

    // Hoist weight: columns are chunk-invariant (chunk stride = 4096 scalars)
    float4 wv[UNROLL];
#pragma unroll
    for (int k = 0; k < UNROLL; k++)
        wv[k] = *(const float4*)(w + k * 1024 + t * 4);

    for (int c = blockIdx.x; c < nchunks; c += gridDim.x) {
        long long base = (long long)c * CHUNK + t;

        // Front-batch 4 independent LDG.128
        float4 xv[UNROLL];
#pragma unroll
        for (int k = 0; k < UNROLL; k++)
            xv[k] = __ldcs(&x4[base + k * THREADS]);

#pragma unroll
        for (int k = 0; k < UNROLL; k++) {
            float4 ov;
            ov.x = xv[k].x * wv[k].x;
            ov.y = xv[k].y * wv[k].y;
            ov.z = xv[k].z * wv[k].z;
            ov.w = xv[k].w * wv[k].w;
            __stcs(&out4[base + k * THREADS], ov);
        }
    }
}

extern "C" void kernel_launch(void* const* d_in, const int* in_sizes, int n_in,
                              void* d_out, int out_size)
{
    const float* x = (const float*)d_in[0];
    const float* w = (const float*)d_in[1];
    float* out = (float*)d_out;

    long long n  = (long long)out_size;  // 4*4096*4096 = 67108864
    int nchunks = (int)(n / (CHUNK * 4)); // 16384 row-chunks

    // GB300: 152 SMs; 8 resident blocks/SM at 256 threads
    const int blocks = 152 * 8;  // 1216

    scale_lastdim_pers_kernel<<<blocks, THREADS>>>(
        (const float4*)x, w, (float4*)out, nchunks);
}

// round 7
// speedup vs baseline: 1.0261x; 1.0261x over previous
#include <cuda_runtime.h>

// out[b, r, c] = x[b, r, c] * weight[c], N = 4096 (power of two)
// HBM stream at ~88% of spec (measured): 4x float4/thread, front-batched loads,
// exact grid cover, pure 32-bit indexing, weight cols thread-invariant.

#define THREADS 256
#define UNROLL  4
// block chunk = 1024 float4 = 4096 scalars = exactly one weight row

__global__ void __launch_bounds__(THREADS) scale_lastdim_u4i_kernel(
    const float4* __restrict__ x4,
    const float*  __restrict__ w,
    float4* __restrict__ out4)
{
    const unsigned t = threadIdx.x;
    const unsigned base = blockIdx.x * (THREADS * UNROLL) + t;

    // Weight columns depend only on threadIdx: block base is a multiple of
    // 4096 scalars, so (global_col & 4095) == (t*4 + k*1024).
    float4 wv[UNROLL];
#pragma unroll
    for (int k = 0; k < UNROLL; k++)
        wv[k] = __ldg((const float4*)(w + k * 1024 + t * 4));  // 16 KB, L1-hit

    // Front-batch 4 independent LDG.128 (streaming: x never reused)
    float4 xv[UNROLL];
#pragma unroll
    for (int k = 0; k < UNROLL; k++)
        xv[k] = __ldcs(&x4[base + k * THREADS]);

#pragma unroll
    for (int k = 0; k < UNROLL; k++) {
        float4 ov;
        ov.x = xv[k].x * wv[k].x;
        ov.y = xv[k].y * wv[k].y;
        ov.z = xv[k].z * wv[k].z;
        ov.w = xv[k].w * wv[k].w;
        __stcs(&out4[base + k * THREADS], ov);
    }
}

extern "C" void kernel_launch(void* const* d_in, const int* in_sizes, int n_in,
                              void* d_out, int out_size)
{
    const float* x = (const float*)d_in[0];
    const float* w = (const float*)d_in[1];
    float* out = (float*)d_out;

    long long n  = (long long)out_size;        // 67108864
    unsigned n4 = (unsigned)(n >> 2);           // 16777216 float4s
    unsigned blocks = n4 / (THREADS * UNROLL);  // 16384, exact cover

    scale_lastdim_u4i_kernel<<<blocks, THREADS>>>(
        (const float4*)x, w, (float4*)out);
}